// round 12
// baseline (speedup 1.0000x reference)
#include <cuda_runtime.h>
#include <math_constants.h>
#include <stdint.h>

#define B_      4
#define N_      16384
#define STRIDE_ 4
#define K_      20
#define K2_     32          // screening candidate count
#define D_      64
#define DK_     67
#define KFS_    68
#define M_      4096
#define NQ_     (B_*M_)     // 16384
#define HID_    128
#define OUT_    128
#define TK_     128         // keys per tile
#define QB_     64          // queries per block (8 warps x 8)

// scratch (no cudaMalloc allowed)
__device__ float    g_kf[(size_t)B_*N_*KFS_];    // fp32 features (pad=0) for exact rerank
__device__ uint4    g_kfqT[(size_t)B_*5*N_];     // int8 features, transposed [b][chunk g][key]
__device__ float    g_kn[B_*N_];                 // key squared norms (fp32, for rerank)
__device__ float2   g_knc[B_*N_];                // (kn, -2*scale) for screening epilogue
__device__ int      g_cand[NQ_*K2_];             // screening candidates
__device__ int      g_nbr[NQ_*K_];               // exact neighbor indices

// monotone float -> uint key (handles negatives); inverse
static __device__ __forceinline__ uint32_t fkey_(float x) {
    uint32_t u = __float_as_uint(x);
    return u ^ (uint32_t)(((int)u >> 31) | 0x80000000);
}
static __device__ __forceinline__ float funkey_(uint32_t k) {
    uint32_t u = (k & 0x80000000u) ? (k ^ 0x80000000u) : ~k;
    return __uint_as_float(u);
}
static __device__ __forceinline__ uint32_t redux_max_(uint32_t v) {
    uint32_t r; asm("redux.sync.max.u32 %0,%1,0xffffffff;" : "=r"(r) : "r"(v)); return r;
}

// ---------------------------------------------------------------------------
// Kernel 1: per-point transform -> kf (fp32 + transposed int8), norms, scale,
// passthrough outputs
// ---------------------------------------------------------------------------
__global__ void __launch_bounds__(256) k_prep(const float* __restrict__ x,
                                              const float* __restrict__ pos,
                                              const float* __restrict__ lfr,
                                              float* __restrict__ outp,
                                              int out_size)
{
    int n = blockIdx.x * blockDim.x + threadIdx.x;
    if (n >= B_*N_) return;
    const float* xr = x + (size_t)n * D_;
    const float* R  = lfr + (size_t)n * 9;
    float r[9];
#pragma unroll
    for (int i = 0; i < 9; i++) r[i] = R[i];

    float kf[KFS_];
#pragma unroll
    for (int i = 0; i < 16; i++) kf[i] = xr[i];
#pragma unroll
    for (int v = 0; v < 16; v++) {
        float b0 = xr[16+3*v+0], b1 = xr[16+3*v+1], b2 = xr[16+3*v+2];
#pragma unroll
        for (int a = 0; a < 3; a++)
            kf[16+3*v+a] = r[0*3+a]*b0 + r[1*3+a]*b1 + r[2*3+a]*b2;
    }
    float p0 = pos[n*3+0], p1 = pos[n*3+1], p2 = pos[n*3+2];
    kf[64] = p0; kf[65] = p1; kf[66] = p2; kf[67] = 0.f;

    float s = 0.f, mxv = 1e-20f;
#pragma unroll
    for (int i = 0; i < KFS_; i++) {
        g_kf[(size_t)n*KFS_ + i] = kf[i];
        s += kf[i]*kf[i];
        mxv = fmaxf(mxv, fabsf(kf[i]));
    }
    g_kn[n] = s;

    // int8 quantization, per-row scale; write transposed [b][g][key]
    const float inv = 127.f / mxv;
    g_knc[n] = make_float2(s, -2.f * mxv * (1.f/127.f));
    const int b  = n >> 14;
    const int ln = n & (N_-1);
    uint32_t qw[20];
#pragma unroll
    for (int g = 0; g < 17; g++) {
        int a0 = __float2int_rn(kf[4*g+0]*inv);
        int a1 = __float2int_rn(kf[4*g+1]*inv);
        int a2 = __float2int_rn(kf[4*g+2]*inv);
        int a3 = __float2int_rn(kf[4*g+3]*inv);
        qw[g] = (uint32_t)(a0 & 0xff) | ((uint32_t)(a1 & 0xff) << 8)
              | ((uint32_t)(a2 & 0xff) << 16) | ((uint32_t)a3 << 24);
    }
    qw[17] = 0u; qw[18] = 0u; qw[19] = 0u;
#pragma unroll
    for (int g = 0; g < 5; g++)
        g_kfqT[((size_t)b*5 + g)*N_ + ln] = make_uint4(qw[4*g], qw[4*g+1], qw[4*g+2], qw[4*g+3]);

    if ((n & 3) == 0) {
        int qid = b*M_ + (ln >> 2);
        const int off_pos = NQ_*OUT_;
        const int off_bat = off_pos + NQ_*3;
        const int off_lf  = off_bat + NQ_;
        if (out_size >= off_lf + NQ_*9) {
            float* pos_out = outp + off_pos;
            float* bat_out = outp + off_bat;
            float* lf_out  = outp + off_lf;
            pos_out[qid*3+0] = p0; pos_out[qid*3+1] = p1; pos_out[qid*3+2] = p2;
            bat_out[qid] = (float)b;
#pragma unroll
            for (int i = 0; i < 9; i++) lf_out[qid*9+i] = r[i];
        }
    }
}

// ---------------------------------------------------------------------------
// Warp-distributed top-32 insert — redux.sync based (proven R10/R11)
// ---------------------------------------------------------------------------
__device__ __forceinline__ void topk_insert(float d2, int gidx,
                                            uint32_t& kdk, int& ki, float& th, int lane)
{
    unsigned m = __ballot_sync(0xffffffffu, d2 < th);
    while (m) {
        int src = __ffs(m) - 1; m &= m - 1;
        float v  = __shfl_sync(0xffffffffu, d2,  src);
        int   vi = __shfl_sync(0xffffffffu, gidx, src);
        if (v < th) {
            uint32_t mx = redux_max_(kdk);
            unsigned vict = __ballot_sync(0xffffffffu, kdk == mx);
            int ml = __ffs(vict) - 1;
            if (lane == ml) { kdk = fkey_(v); ki = vi; }
            th = funkey_(redux_max_(kdk));
        }
    }
}

// ---------------------------------------------------------------------------
// Kernel 2: int8 dp4a screening KNN, transposed-key direct-LDG version.
// No key staging, no inner-loop barriers. Warp owns 8 queries.
// Keys: coalesced LDG.128 from g_kfqT (L1/L2 hot). Queries: smem broadcast.
// d2' = kn - 2*s_q*s_k*dot_int (qn dropped).
// ---------------------------------------------------------------------------
__global__ void __launch_bounds__(256) k_knn_i8()
{
    __shared__ uint4 skq4[QB_*5];

    const int tid = threadIdx.x, lane = tid & 31, w = tid >> 5;
    const int qbase = blockIdx.x * QB_;
    const int b = qbase >> 12;
    const int kb0 = b * N_;
    const uint4* __restrict__ T = g_kfqT + (size_t)b*5*N_;
    const float2* __restrict__ knc = g_knc + kb0;

    // stage 64 query rows (int8) from the transposed array
    for (int i = tid; i < QB_*5; i += 256) {
        int row = i / 5, g = i - row*5;
        int ptl = ((qbase + row) - b*M_) * STRIDE_;
        skq4[row*5 + g] = T[(size_t)g*N_ + ptl];
    }

    // per-query quant scales
    float sq[8];
#pragma unroll
    for (int j = 0; j < 8; j++) {
        int ptl = ((qbase + w*8 + j) - b*M_) * STRIDE_;
        sq[j] = -0.5f * knc[ptl].y;
    }

    uint32_t kdk[8];
    float th[8];
    int   ki[8];
    const uint32_t KINF = fkey_(CUDART_INF_F);
#pragma unroll
    for (int j = 0; j < 8; j++) { kdk[j] = KINF; ki[j] = 0; th[j] = CUDART_INF_F; }
    const uint4* qb = skq4 + (w*8)*5;

    __syncthreads();   // queries staged (only barrier in the kernel)

    for (int t = 0; t < N_/TK_; t++) {
        const int kl = t*TK_ + lane;    // batch-local key of group 0
        int acc[8][4];
#pragma unroll
        for (int q = 0; q < 8; q++) { acc[q][0]=0; acc[q][1]=0; acc[q][2]=0; acc[q][3]=0; }

#pragma unroll
        for (int g = 0; g < 5; g++) {
            const uint4* Tg = T + (size_t)g*N_ + kl;
            uint4 k0 = Tg[0];
            uint4 k1 = Tg[32];
            uint4 k2 = Tg[64];
            uint4 k3 = Tg[96];
#pragma unroll
            for (int q = 0; q < 8; q++) {
                uint4 qv = qb[q*5 + g];   // broadcast LDS.128
                acc[q][0] = __dp4a((int)qv.x, (int)k0.x, acc[q][0]);
                acc[q][1] = __dp4a((int)qv.x, (int)k1.x, acc[q][1]);
                acc[q][2] = __dp4a((int)qv.x, (int)k2.x, acc[q][2]);
                acc[q][3] = __dp4a((int)qv.x, (int)k3.x, acc[q][3]);
                acc[q][0] = __dp4a((int)qv.y, (int)k0.y, acc[q][0]);
                acc[q][1] = __dp4a((int)qv.y, (int)k1.y, acc[q][1]);
                acc[q][2] = __dp4a((int)qv.y, (int)k2.y, acc[q][2]);
                acc[q][3] = __dp4a((int)qv.y, (int)k3.y, acc[q][3]);
                acc[q][0] = __dp4a((int)qv.z, (int)k0.z, acc[q][0]);
                acc[q][1] = __dp4a((int)qv.z, (int)k1.z, acc[q][1]);
                acc[q][2] = __dp4a((int)qv.z, (int)k2.z, acc[q][2]);
                acc[q][3] = __dp4a((int)qv.z, (int)k3.z, acc[q][3]);
                acc[q][0] = __dp4a((int)qv.w, (int)k0.w, acc[q][0]);
                acc[q][1] = __dp4a((int)qv.w, (int)k1.w, acc[q][1]);
                acc[q][2] = __dp4a((int)qv.w, (int)k2.w, acc[q][2]);
                acc[q][3] = __dp4a((int)qv.w, (int)k3.w, acc[q][3]);
            }
        }

        const float2 kc0 = knc[kl], kc1 = knc[kl+32], kc2 = knc[kl+64], kc3 = knc[kl+96];
        const int gi = kb0 + kl;
#pragma unroll
        for (int q = 0; q < 8; q++) {
            float d20 = fmaf((float)acc[q][0], sq[q]*kc0.y, kc0.x);
            float d21 = fmaf((float)acc[q][1], sq[q]*kc1.y, kc1.x);
            float d22 = fmaf((float)acc[q][2], sq[q]*kc2.y, kc2.x);
            float d23 = fmaf((float)acc[q][3], sq[q]*kc3.y, kc3.x);
            float mn = fminf(fminf(d20, d21), fminf(d22, d23));
            if (__ballot_sync(0xffffffffu, mn < th[q])) {
                topk_insert(d20, gi,    kdk[q], ki[q], th[q], lane);
                topk_insert(d21, gi+32, kdk[q], ki[q], th[q], lane);
                topk_insert(d22, gi+64, kdk[q], ki[q], th[q], lane);
                topk_insert(d23, gi+96, kdk[q], ki[q], th[q], lane);
            }
        }
    }

#pragma unroll
    for (int q = 0; q < 8; q++)
        g_cand[(size_t)(qbase + w*8 + q)*K2_ + lane] = ki[q];
}

// ---------------------------------------------------------------------------
// Kernel 2b: exact fp32 re-rank of 32 candidates -> top-20 set.
// ---------------------------------------------------------------------------
__global__ void __launch_bounds__(256) k_rerank()
{
    const int tid = threadIdx.x, lane = tid & 31, w = tid >> 5;
    const int q = blockIdx.x * 8 + w;
    const int b = q >> 12;
    const int pt = b*N_ + (q - b*M_) * STRIDE_;

    const int cand = g_cand[(size_t)q*K2_ + lane];
    const float4* qr = (const float4*)(g_kf + (size_t)pt*KFS_);
    const float4* kr = (const float4*)(g_kf + (size_t)cand*KFS_);
    float dot = 0.f;
#pragma unroll
    for (int g = 0; g < 17; g++) {
        float4 a = qr[g], c = kr[g];
        dot = fmaf(a.x,c.x, fmaf(a.y,c.y, fmaf(a.z,c.z, fmaf(a.w,c.w, dot))));
    }
    float d2 = g_kn[cand] - 2.f*dot;

#pragma unroll
    for (int r = 0; r < K_; r++) {
        float mv = d2; int ml = lane;
#pragma unroll
        for (int off = 16; off; off >>= 1) {
            float om = __shfl_xor_sync(0xffffffffu, mv, off);
            int   ol = __shfl_xor_sync(0xffffffffu, ml, off);
            if (om < mv || (om == mv && ol < ml)) { mv = om; ml = ol; }
        }
        if (lane == ml) { g_nbr[q*K_ + r] = cand; d2 = CUDART_INF_F; }
    }
}

// ---------------------------------------------------------------------------
// Kernel 3: edge MLP + maxpool — vectorized activation reads (LDS.128).
// ---------------------------------------------------------------------------
__global__ void __launch_bounds__(256) k_mlp(const float* __restrict__ x,
                                             const float* __restrict__ lfr,
                                             const float* __restrict__ W1,
                                             const float* __restrict__ b1,
                                             const float* __restrict__ W2,
                                             const float* __restrict__ b2,
                                             float* __restrict__ outp)
{
    __shared__ __align__(16) float sxd[8][D_];
    __shared__ float slf[8][12];
    __shared__ __align__(16) float srel[8][4][D_];
    __shared__ __align__(16) float srl[8][4][D_];
    __shared__ __align__(16) float sa1[8][4][HID_];

    const int tid = threadIdx.x, lane = tid & 31, w = tid >> 5;
    const int q  = blockIdx.x * 8 + w;
    const int b  = q >> 12;
    const int pt = b*N_ + (q - b*M_) * STRIDE_;

    for (int d = lane; d < D_; d += 32) sxd[w][d] = x[(size_t)pt*D_ + d];
    if (lane < 9) slf[w][lane] = lfr[(size_t)pt*9 + lane];
    __syncwarp();

    const int c4 = lane * 4;
    float4 base = *(const float4*)(b1 + c4);
#pragma unroll 8
    for (int d = 0; d < D_; d++) {
        float xv = sxd[w][d];
        float4 w4 = __ldg((const float4*)(W1 + d*HID_ + c4));
        base.x += xv*w4.x; base.y += xv*w4.y; base.z += xv*w4.z; base.w += xv*w4.w;
    }
    const float4 b2v = __ldg((const float4*)(b2 + c4));
    float4 mx = make_float4(-CUDART_INF_F, -CUDART_INF_F, -CUDART_INF_F, -CUDART_INF_F);

    for (int grp = 0; grp < 5; grp++) {
        __syncwarp();
        int s = 0;
        if (lane < 4) s = g_nbr[q*K_ + grp*4 + lane];
        const int ss0 = __shfl_sync(0xffffffffu, s, 0);
        const int ss1 = __shfl_sync(0xffffffffu, s, 1);
        const int ss2 = __shfl_sync(0xffffffffu, s, 2);
        const int ss3 = __shfl_sync(0xffffffffu, s, 3);
        {
            const float* xs0 = x + (size_t)ss0 * D_;
            const float* xs1 = x + (size_t)ss1 * D_;
            const float* xs2 = x + (size_t)ss2 * D_;
            const float* xs3 = x + (size_t)ss3 * D_;
#pragma unroll
            for (int d = lane; d < D_; d += 32) {
                float xd = sxd[w][d];
                srel[w][0][d] = xs0[d] - xd;
                srel[w][1][d] = xs1[d] - xd;
                srel[w][2][d] = xs2[d] - xd;
                srel[w][3][d] = xs3[d] - xd;
            }
        }
        __syncwarp();
        // rotate rel -> rel_local with R = lf_dst
#pragma unroll
        for (int t = 0; t < 8; t++) {
            int item = lane + 32*t;
            int e = item >> 6;
            int d = item & 63;
            float v;
            if (d < 16) v = srel[w][e][d];
            else {
                int dd = d - 16;
                int a  = dd % 3;
                int vb = 16 + dd - a;
                v = slf[w][a*3+0]*srel[w][e][vb]
                  + slf[w][a*3+1]*srel[w][e][vb+1]
                  + slf[w][a*3+2]*srel[w][e][vb+2];
            }
            srl[w][e][d] = v;
        }
        __syncwarp();

        float4 ac0 = {0,0,0,0}, ac1 = {0,0,0,0}, ac2 = {0,0,0,0}, ac3 = {0,0,0,0};
#pragma unroll 2
        for (int d = 0; d < D_; d += 4) {
            float4 r0 = *(const float4*)&srl[w][0][d];
            float4 r1 = *(const float4*)&srl[w][1][d];
            float4 r2 = *(const float4*)&srl[w][2][d];
            float4 r3 = *(const float4*)&srl[w][3][d];
#pragma unroll
            for (int dd = 0; dd < 4; dd++) {
                float4 w4 = __ldg((const float4*)(W1 + (D_+d+dd)*HID_ + c4));
                float a0 = (&r0.x)[dd], a1 = (&r1.x)[dd], a2 = (&r2.x)[dd], a3 = (&r3.x)[dd];
                ac0.x += a0*w4.x; ac0.y += a0*w4.y; ac0.z += a0*w4.z; ac0.w += a0*w4.w;
                ac1.x += a1*w4.x; ac1.y += a1*w4.y; ac1.z += a1*w4.z; ac1.w += a1*w4.w;
                ac2.x += a2*w4.x; ac2.y += a2*w4.y; ac2.z += a2*w4.z; ac2.w += a2*w4.w;
                ac3.x += a3*w4.x; ac3.y += a3*w4.y; ac3.z += a3*w4.z; ac3.w += a3*w4.w;
            }
        }
        {
            float4 a;
            a.x = fmaxf(base.x+ac0.x,0.f); a.y = fmaxf(base.y+ac0.y,0.f);
            a.z = fmaxf(base.z+ac0.z,0.f); a.w = fmaxf(base.w+ac0.w,0.f);
            *(float4*)&sa1[w][0][c4] = a;
            a.x = fmaxf(base.x+ac1.x,0.f); a.y = fmaxf(base.y+ac1.y,0.f);
            a.z = fmaxf(base.z+ac1.z,0.f); a.w = fmaxf(base.w+ac1.w,0.f);
            *(float4*)&sa1[w][1][c4] = a;
            a.x = fmaxf(base.x+ac2.x,0.f); a.y = fmaxf(base.y+ac2.y,0.f);
            a.z = fmaxf(base.z+ac2.z,0.f); a.w = fmaxf(base.w+ac2.w,0.f);
            *(float4*)&sa1[w][2][c4] = a;
            a.x = fmaxf(base.x+ac3.x,0.f); a.y = fmaxf(base.y+ac3.y,0.f);
            a.z = fmaxf(base.z+ac3.z,0.f); a.w = fmaxf(base.w+ac3.w,0.f);
            *(float4*)&sa1[w][3][c4] = a;
        }
        __syncwarp();

        float4 m0 = b2v, m1 = b2v, m2 = b2v, m3 = b2v;
#pragma unroll 2
        for (int j = 0; j < HID_; j += 4) {
            float4 a0v = *(const float4*)&sa1[w][0][j];
            float4 a1v = *(const float4*)&sa1[w][1][j];
            float4 a2v = *(const float4*)&sa1[w][2][j];
            float4 a3v = *(const float4*)&sa1[w][3][j];
#pragma unroll
            for (int jj = 0; jj < 4; jj++) {
                float4 w4 = __ldg((const float4*)(W2 + (j+jj)*HID_ + c4));
                float a0 = (&a0v.x)[jj], a1 = (&a1v.x)[jj], a2 = (&a2v.x)[jj], a3 = (&a3v.x)[jj];
                m0.x += a0*w4.x; m0.y += a0*w4.y; m0.z += a0*w4.z; m0.w += a0*w4.w;
                m1.x += a1*w4.x; m1.y += a1*w4.y; m1.z += a1*w4.z; m1.w += a1*w4.w;
                m2.x += a2*w4.x; m2.y += a2*w4.y; m2.z += a2*w4.z; m2.w += a2*w4.w;
                m3.x += a3*w4.x; m3.y += a3*w4.y; m3.z += a3*w4.z; m3.w += a3*w4.w;
            }
        }
        mx.x = fmaxf(fmaxf(fmaxf(fmaxf(mx.x, m0.x), m1.x), m2.x), m3.x);
        mx.y = fmaxf(fmaxf(fmaxf(fmaxf(mx.y, m0.y), m1.y), m2.y), m3.y);
        mx.z = fmaxf(fmaxf(fmaxf(fmaxf(mx.z, m0.z), m1.z), m2.z), m3.z);
        mx.w = fmaxf(fmaxf(fmaxf(fmaxf(mx.w, m0.w), m1.w), m2.w), m3.w);
    }

    *(float4*)(outp + (size_t)q*OUT_ + c4) = mx;
}

// ---------------------------------------------------------------------------
extern "C" void kernel_launch(void* const* d_in, const int* in_sizes, int n_in,
                              void* d_out, int out_size)
{
    const float* x   = (const float*)d_in[0];
    const float* pos = (const float*)d_in[1];
    const float* lfr = (const float*)d_in[2];
    const float* W1  = (const float*)d_in[4];
    const float* b1  = (const float*)d_in[5];
    const float* W2  = (const float*)d_in[6];
    const float* b2  = (const float*)d_in[7];
    float* outp = (float*)d_out;

    k_prep<<<(B_*N_ + 255)/256, 256>>>(x, pos, lfr, outp, out_size);
    k_knn_i8<<<NQ_/QB_, 256>>>();
    k_rerank<<<NQ_/8, 256>>>();
    k_mlp<<<NQ_/8, 256>>>(x, lfr, W1, b1, W2, b2, outp);
}

// round 13
// speedup vs baseline: 1.0636x; 1.0636x over previous
#include <cuda_runtime.h>
#include <math_constants.h>
#include <stdint.h>

#define B_      4
#define N_      16384
#define STRIDE_ 4
#define K_      20
#define K2_     32          // screening candidate count
#define D_      64
#define DK_     67
#define KFS_    68
#define M_      4096
#define NQ_     (B_*M_)     // 16384
#define HID_    128
#define OUT_    128
#define TK_     128         // keys per tile
#define QB_     64          // queries per block (8 warps x 8)
#define ROWQ_   20          // uints per int8 feature row (68 dims + 12 pad)

// scratch (no cudaMalloc allowed)
__device__ float    g_kf[(size_t)B_*N_*KFS_];   // fp32 features (pad=0) for exact rerank
__device__ uint32_t g_kfq[(size_t)B_*N_*ROWQ_]; // int8 features (pads=0) for screening
__device__ float    g_kn[B_*N_];                // key squared norms (fp32)
__device__ float    g_ksc[B_*N_];               // per-row quant scale
__device__ int      g_cand[NQ_*K2_];            // screening candidates
__device__ int      g_nbr[NQ_*K_];              // exact neighbor indices

// monotone float -> uint key (handles negatives); inverse
static __device__ __forceinline__ uint32_t fkey_(float x) {
    uint32_t u = __float_as_uint(x);
    return u ^ (uint32_t)(((int)u >> 31) | 0x80000000);
}
static __device__ __forceinline__ float funkey_(uint32_t k) {
    uint32_t u = (k & 0x80000000u) ? (k ^ 0x80000000u) : ~k;
    return __uint_as_float(u);
}
static __device__ __forceinline__ uint32_t redux_max_(uint32_t v) {
    uint32_t r; asm("redux.sync.max.u32 %0,%1,0xffffffff;" : "=r"(r) : "r"(v)); return r;
}

// ---------------------------------------------------------------------------
// Kernel 1: per-point transform -> kf (fp32 + int8), norms, scale, passthrough
// (byte-identical to R11)
// ---------------------------------------------------------------------------
__global__ void __launch_bounds__(256) k_prep(const float* __restrict__ x,
                                              const float* __restrict__ pos,
                                              const float* __restrict__ lfr,
                                              float* __restrict__ outp,
                                              int out_size)
{
    int n = blockIdx.x * blockDim.x + threadIdx.x;
    if (n >= B_*N_) return;
    const float* xr = x + (size_t)n * D_;
    const float* R  = lfr + (size_t)n * 9;
    float r[9];
#pragma unroll
    for (int i = 0; i < 9; i++) r[i] = R[i];

    float kf[KFS_];
#pragma unroll
    for (int i = 0; i < 16; i++) kf[i] = xr[i];
#pragma unroll
    for (int v = 0; v < 16; v++) {
        float b0 = xr[16+3*v+0], b1 = xr[16+3*v+1], b2 = xr[16+3*v+2];
#pragma unroll
        for (int a = 0; a < 3; a++)
            kf[16+3*v+a] = r[0*3+a]*b0 + r[1*3+a]*b1 + r[2*3+a]*b2;
    }
    float p0 = pos[n*3+0], p1 = pos[n*3+1], p2 = pos[n*3+2];
    kf[64] = p0; kf[65] = p1; kf[66] = p2; kf[67] = 0.f;

    float s = 0.f, mxv = 1e-20f;
#pragma unroll
    for (int i = 0; i < KFS_; i++) {
        g_kf[(size_t)n*KFS_ + i] = kf[i];
        s += kf[i]*kf[i];
        mxv = fmaxf(mxv, fabsf(kf[i]));
    }
    g_kn[n] = s;

    const float inv = 127.f / mxv;
    g_ksc[n] = mxv * (1.f/127.f);
    uint32_t* qr = g_kfq + (size_t)n*ROWQ_;
#pragma unroll
    for (int g = 0; g < 17; g++) {
        int a0 = __float2int_rn(kf[4*g+0]*inv);
        int a1 = __float2int_rn(kf[4*g+1]*inv);
        int a2 = __float2int_rn(kf[4*g+2]*inv);
        int a3 = __float2int_rn(kf[4*g+3]*inv);
        qr[g] = (uint32_t)(a0 & 0xff) | ((uint32_t)(a1 & 0xff) << 8)
              | ((uint32_t)(a2 & 0xff) << 16) | ((uint32_t)a3 << 24);
    }
    qr[17] = 0u; qr[18] = 0u; qr[19] = 0u;

    if ((n & 3) == 0) {
        int b   = n >> 14;
        int qid = b*M_ + ((n & (N_-1)) >> 2);
        const int off_pos = NQ_*OUT_;
        const int off_bat = off_pos + NQ_*3;
        const int off_lf  = off_bat + NQ_;
        if (out_size >= off_lf + NQ_*9) {
            float* pos_out = outp + off_pos;
            float* bat_out = outp + off_bat;
            float* lf_out  = outp + off_lf;
            pos_out[qid*3+0] = p0; pos_out[qid*3+1] = p1; pos_out[qid*3+2] = p2;
            bat_out[qid] = (float)b;
#pragma unroll
            for (int i = 0; i < 9; i++) lf_out[qid*9+i] = r[i];
        }
    }
}

// ---------------------------------------------------------------------------
// Warp-distributed top-32 insert — redux.sync based (proven R10/R11)
// ---------------------------------------------------------------------------
__device__ __forceinline__ void topk_insert(float d2, int gidx,
                                            uint32_t& kdk, int& ki, float& th, int lane)
{
    unsigned m = __ballot_sync(0xffffffffu, d2 < th);
    while (m) {
        int src = __ffs(m) - 1; m &= m - 1;
        float v  = __shfl_sync(0xffffffffu, d2,  src);
        int   vi = __shfl_sync(0xffffffffu, gidx, src);
        if (v < th) {
            uint32_t mx = redux_max_(kdk);
            unsigned vict = __ballot_sync(0xffffffffu, kdk == mx);
            int ml = __ffs(vict) - 1;
            if (lane == ml) { kdk = fkey_(v); ki = vi; }
            th = funkey_(redux_max_(kdk));
        }
    }
}

// ---------------------------------------------------------------------------
// Kernel 2: int8 dp4a screening KNN (R11, proven: smem double-buffered tiles).
// ---------------------------------------------------------------------------
__global__ void __launch_bounds__(256) k_knn_i8()
{
    extern __shared__ uint32_t sh[];
    uint32_t* skq  = sh;                              // [QB_][20]
    uint32_t* skey = sh + QB_*ROWQ_;                  // [2][TK_][20]
    float*    skn  = (float*)(sh + QB_*ROWQ_ + 2*TK_*ROWQ_);          // [2][TK_]
    float*    ssc  = (float*)(sh + QB_*ROWQ_ + 2*TK_*ROWQ_ + 2*TK_);  // [2][TK_]

    const int tid = threadIdx.x, lane = tid & 31, w = tid >> 5;
    const int qbase = blockIdx.x * QB_;
    const int b = qbase >> 12;
    const int kb0 = b * N_;

    for (int i = tid; i < QB_*5; i += 256) {
        int row = i / 5, g = i - row*5;
        int pt = kb0 + ((qbase + row) - b*M_) * STRIDE_;
        *(uint4*)(skq + row*ROWQ_ + 4*g) = *(const uint4*)(g_kfq + (size_t)pt*ROWQ_ + 4*g);
    }
    for (int i = tid; i < TK_*5; i += 256) {
        int row = i / 5, g = i - row*5;
        *(uint4*)(skey + row*ROWQ_ + 4*g) = *(const uint4*)(g_kfq + (size_t)(kb0 + row)*ROWQ_ + 4*g);
    }
    if (tid < TK_) { skn[tid] = g_kn[kb0 + tid]; ssc[tid] = g_ksc[kb0 + tid]; }

    float sq[8];
#pragma unroll
    for (int j = 0; j < 8; j++)
        sq[j] = g_ksc[kb0 + ((qbase + w*8 + j) - b*M_) * STRIDE_];

    uint32_t kdk[8];
    float th[8];
    int   ki[8];
    const uint32_t KINF = fkey_(CUDART_INF_F);
#pragma unroll
    for (int j = 0; j < 8; j++) { kdk[j] = KINF; ki[j] = 0; th[j] = CUDART_INF_F; }
    const uint32_t* qb = skq + (w*8)*ROWQ_;

    __syncthreads();

    for (int t = 0; t < N_/TK_; t++) {
        const int buf = t & 1;
        if (t + 1 < N_/TK_) {
            uint32_t* dst = skey + (buf^1)*TK_*ROWQ_;
            const uint32_t* src = g_kfq + (size_t)(kb0 + (t+1)*TK_)*ROWQ_;
            for (int i = tid; i < TK_*5; i += 256) {
                int row = i / 5, g = i - row*5;
                *(uint4*)(dst + row*ROWQ_ + 4*g) = *(const uint4*)(src + (size_t)row*ROWQ_ + 4*g);
            }
            if (tid < TK_) {
                skn[(buf^1)*TK_ + tid] = g_kn[kb0 + (t+1)*TK_ + tid];
                ssc[(buf^1)*TK_ + tid] = g_ksc[kb0 + (t+1)*TK_ + tid];
            }
        }

        const uint32_t* kb = skey + buf*TK_*ROWQ_;
        int acc[8][4];
#pragma unroll
        for (int q = 0; q < 8; q++) { acc[q][0]=0; acc[q][1]=0; acc[q][2]=0; acc[q][3]=0; }

#pragma unroll
        for (int g = 0; g < 5; g++) {
            uint4 k0 = *(const uint4*)(kb + (lane     )*ROWQ_ + 4*g);
            uint4 k1 = *(const uint4*)(kb + (lane + 32)*ROWQ_ + 4*g);
            uint4 k2 = *(const uint4*)(kb + (lane + 64)*ROWQ_ + 4*g);
            uint4 k3 = *(const uint4*)(kb + (lane + 96)*ROWQ_ + 4*g);
#pragma unroll
            for (int q = 0; q < 8; q++) {
                uint4 qv = *(const uint4*)(qb + q*ROWQ_ + 4*g);   // broadcast LDS.128
                acc[q][0] = __dp4a((int)qv.x, (int)k0.x, acc[q][0]);
                acc[q][1] = __dp4a((int)qv.x, (int)k1.x, acc[q][1]);
                acc[q][2] = __dp4a((int)qv.x, (int)k2.x, acc[q][2]);
                acc[q][3] = __dp4a((int)qv.x, (int)k3.x, acc[q][3]);
                acc[q][0] = __dp4a((int)qv.y, (int)k0.y, acc[q][0]);
                acc[q][1] = __dp4a((int)qv.y, (int)k1.y, acc[q][1]);
                acc[q][2] = __dp4a((int)qv.y, (int)k2.y, acc[q][2]);
                acc[q][3] = __dp4a((int)qv.y, (int)k3.y, acc[q][3]);
                acc[q][0] = __dp4a((int)qv.z, (int)k0.z, acc[q][0]);
                acc[q][1] = __dp4a((int)qv.z, (int)k1.z, acc[q][1]);
                acc[q][2] = __dp4a((int)qv.z, (int)k2.z, acc[q][2]);
                acc[q][3] = __dp4a((int)qv.z, (int)k3.z, acc[q][3]);
                acc[q][0] = __dp4a((int)qv.w, (int)k0.w, acc[q][0]);
                acc[q][1] = __dp4a((int)qv.w, (int)k1.w, acc[q][1]);
                acc[q][2] = __dp4a((int)qv.w, (int)k2.w, acc[q][2]);
                acc[q][3] = __dp4a((int)qv.w, (int)k3.w, acc[q][3]);
            }
        }

        const float* knb = skn + buf*TK_;
        const float* scb = ssc + buf*TK_;
        const float kn0 = knb[lane], kn1 = knb[lane+32], kn2 = knb[lane+64], kn3 = knb[lane+96];
        const float c0 = -2.f*scb[lane],    c1 = -2.f*scb[lane+32];
        const float c2 = -2.f*scb[lane+64], c3 = -2.f*scb[lane+96];
        const int gi = kb0 + t*TK_ + lane;
#pragma unroll
        for (int q = 0; q < 8; q++) {
            float d20 = fmaf((float)acc[q][0], sq[q]*c0, kn0);
            float d21 = fmaf((float)acc[q][1], sq[q]*c1, kn1);
            float d22 = fmaf((float)acc[q][2], sq[q]*c2, kn2);
            float d23 = fmaf((float)acc[q][3], sq[q]*c3, kn3);
            float mn = fminf(fminf(d20, d21), fminf(d22, d23));
            if (__ballot_sync(0xffffffffu, mn < th[q])) {
                topk_insert(d20, gi,    kdk[q], ki[q], th[q], lane);
                topk_insert(d21, gi+32, kdk[q], ki[q], th[q], lane);
                topk_insert(d22, gi+64, kdk[q], ki[q], th[q], lane);
                topk_insert(d23, gi+96, kdk[q], ki[q], th[q], lane);
            }
        }
        __syncthreads();
    }

#pragma unroll
    for (int q = 0; q < 8; q++)
        g_cand[(size_t)(qbase + w*8 + q)*K2_ + lane] = ki[q];
}

// ---------------------------------------------------------------------------
// Kernel 2b: exact fp32 re-rank of 32 candidates -> top-20 set.
// ---------------------------------------------------------------------------
__global__ void __launch_bounds__(256) k_rerank()
{
    const int tid = threadIdx.x, lane = tid & 31, w = tid >> 5;
    const int q = blockIdx.x * 8 + w;
    const int b = q >> 12;
    const int pt = b*N_ + (q - b*M_) * STRIDE_;

    const int cand = g_cand[(size_t)q*K2_ + lane];
    const float4* qr = (const float4*)(g_kf + (size_t)pt*KFS_);
    const float4* kr = (const float4*)(g_kf + (size_t)cand*KFS_);
    float dot = 0.f;
#pragma unroll
    for (int g = 0; g < 17; g++) {
        float4 a = qr[g], c = kr[g];
        dot = fmaf(a.x,c.x, fmaf(a.y,c.y, fmaf(a.z,c.z, fmaf(a.w,c.w, dot))));
    }
    float d2 = g_kn[cand] - 2.f*dot;

#pragma unroll
    for (int r = 0; r < K_; r++) {
        float mv = d2; int ml = lane;
#pragma unroll
        for (int off = 16; off; off >>= 1) {
            float om = __shfl_xor_sync(0xffffffffu, mv, off);
            int   ol = __shfl_xor_sync(0xffffffffu, ml, off);
            if (om < mv || (om == mv && ol < ml)) { mv = om; ml = ol; }
        }
        if (lane == ml) { g_nbr[q*K_ + r] = cand; d2 = CUDART_INF_F; }
    }
}

// ---------------------------------------------------------------------------
// Kernel 3: edge MLP + maxpool — vectorized LDS reads + occupancy 4 blocks/SM.
// ---------------------------------------------------------------------------
__global__ void __launch_bounds__(256, 4) k_mlp(const float* __restrict__ x,
                                                const float* __restrict__ lfr,
                                                const float* __restrict__ W1,
                                                const float* __restrict__ b1,
                                                const float* __restrict__ W2,
                                                const float* __restrict__ b2,
                                                float* __restrict__ outp)
{
    __shared__ __align__(16) float sxd[8][D_];
    __shared__ float slf[8][12];
    __shared__ __align__(16) float srel[8][4][D_];
    __shared__ __align__(16) float srl[8][4][D_];
    __shared__ __align__(16) float sa1[8][4][HID_];

    const int tid = threadIdx.x, lane = tid & 31, w = tid >> 5;
    const int q  = blockIdx.x * 8 + w;
    const int b  = q >> 12;
    const int pt = b*N_ + (q - b*M_) * STRIDE_;

    for (int d = lane; d < D_; d += 32) sxd[w][d] = x[(size_t)pt*D_ + d];
    if (lane < 9) slf[w][lane] = lfr[(size_t)pt*9 + lane];
    __syncwarp();

    const int c4 = lane * 4;
    float4 base = *(const float4*)(b1 + c4);
#pragma unroll 8
    for (int d = 0; d < D_; d++) {
        float xv = sxd[w][d];
        float4 w4 = __ldg((const float4*)(W1 + d*HID_ + c4));
        base.x += xv*w4.x; base.y += xv*w4.y; base.z += xv*w4.z; base.w += xv*w4.w;
    }
    const float4 b2v = __ldg((const float4*)(b2 + c4));
    float4 mx = make_float4(-CUDART_INF_F, -CUDART_INF_F, -CUDART_INF_F, -CUDART_INF_F);

    for (int grp = 0; grp < 5; grp++) {
        __syncwarp();
        int s = 0;
        if (lane < 4) s = g_nbr[q*K_ + grp*4 + lane];
        const int ss0 = __shfl_sync(0xffffffffu, s, 0);
        const int ss1 = __shfl_sync(0xffffffffu, s, 1);
        const int ss2 = __shfl_sync(0xffffffffu, s, 2);
        const int ss3 = __shfl_sync(0xffffffffu, s, 3);
        {
            const float* xs0 = x + (size_t)ss0 * D_;
            const float* xs1 = x + (size_t)ss1 * D_;
            const float* xs2 = x + (size_t)ss2 * D_;
            const float* xs3 = x + (size_t)ss3 * D_;
#pragma unroll
            for (int d = lane; d < D_; d += 32) {
                float xd = sxd[w][d];
                srel[w][0][d] = xs0[d] - xd;
                srel[w][1][d] = xs1[d] - xd;
                srel[w][2][d] = xs2[d] - xd;
                srel[w][3][d] = xs3[d] - xd;
            }
        }
        __syncwarp();
        // rotate rel -> rel_local with R = lf_dst
#pragma unroll
        for (int t = 0; t < 8; t++) {
            int item = lane + 32*t;
            int e = item >> 6;
            int d = item & 63;
            float v;
            if (d < 16) v = srel[w][e][d];
            else {
                int dd = d - 16;
                int a  = dd % 3;
                int vb = 16 + dd - a;
                v = slf[w][a*3+0]*srel[w][e][vb]
                  + slf[w][a*3+1]*srel[w][e][vb+1]
                  + slf[w][a*3+2]*srel[w][e][vb+2];
            }
            srl[w][e][d] = v;
        }
        __syncwarp();

        float4 ac0 = {0,0,0,0}, ac1 = {0,0,0,0}, ac2 = {0,0,0,0}, ac3 = {0,0,0,0};
#pragma unroll 2
        for (int d = 0; d < D_; d += 4) {
            float4 r0 = *(const float4*)&srl[w][0][d];
            float4 r1 = *(const float4*)&srl[w][1][d];
            float4 r2 = *(const float4*)&srl[w][2][d];
            float4 r3 = *(const float4*)&srl[w][3][d];
#pragma unroll
            for (int dd = 0; dd < 4; dd++) {
                float4 w4 = __ldg((const float4*)(W1 + (D_+d+dd)*HID_ + c4));
                float a0 = (&r0.x)[dd], a1 = (&r1.x)[dd], a2 = (&r2.x)[dd], a3 = (&r3.x)[dd];
                ac0.x += a0*w4.x; ac0.y += a0*w4.y; ac0.z += a0*w4.z; ac0.w += a0*w4.w;
                ac1.x += a1*w4.x; ac1.y += a1*w4.y; ac1.z += a1*w4.z; ac1.w += a1*w4.w;
                ac2.x += a2*w4.x; ac2.y += a2*w4.y; ac2.z += a2*w4.z; ac2.w += a2*w4.w;
                ac3.x += a3*w4.x; ac3.y += a3*w4.y; ac3.z += a3*w4.z; ac3.w += a3*w4.w;
            }
        }
        {
            float4 a;
            a.x = fmaxf(base.x+ac0.x,0.f); a.y = fmaxf(base.y+ac0.y,0.f);
            a.z = fmaxf(base.z+ac0.z,0.f); a.w = fmaxf(base.w+ac0.w,0.f);
            *(float4*)&sa1[w][0][c4] = a;
            a.x = fmaxf(base.x+ac1.x,0.f); a.y = fmaxf(base.y+ac1.y,0.f);
            a.z = fmaxf(base.z+ac1.z,0.f); a.w = fmaxf(base.w+ac1.w,0.f);
            *(float4*)&sa1[w][1][c4] = a;
            a.x = fmaxf(base.x+ac2.x,0.f); a.y = fmaxf(base.y+ac2.y,0.f);
            a.z = fmaxf(base.z+ac2.z,0.f); a.w = fmaxf(base.w+ac2.w,0.f);
            *(float4*)&sa1[w][2][c4] = a;
            a.x = fmaxf(base.x+ac3.x,0.f); a.y = fmaxf(base.y+ac3.y,0.f);
            a.z = fmaxf(base.z+ac3.z,0.f); a.w = fmaxf(base.w+ac3.w,0.f);
            *(float4*)&sa1[w][3][c4] = a;
        }
        __syncwarp();

        float4 m0 = b2v, m1 = b2v, m2 = b2v, m3 = b2v;
#pragma unroll 2
        for (int j = 0; j < HID_; j += 4) {
            float4 a0v = *(const float4*)&sa1[w][0][j];
            float4 a1v = *(const float4*)&sa1[w][1][j];
            float4 a2v = *(const float4*)&sa1[w][2][j];
            float4 a3v = *(const float4*)&sa1[w][3][j];
#pragma unroll
            for (int jj = 0; jj < 4; jj++) {
                float4 w4 = __ldg((const float4*)(W2 + (j+jj)*HID_ + c4));
                float a0 = (&a0v.x)[jj], a1 = (&a1v.x)[jj], a2 = (&a2v.x)[jj], a3 = (&a3v.x)[jj];
                m0.x += a0*w4.x; m0.y += a0*w4.y; m0.z += a0*w4.z; m0.w += a0*w4.w;
                m1.x += a1*w4.x; m1.y += a1*w4.y; m1.z += a1*w4.z; m1.w += a1*w4.w;
                m2.x += a2*w4.x; m2.y += a2*w4.y; m2.z += a2*w4.z; m2.w += a2*w4.w;
                m3.x += a3*w4.x; m3.y += a3*w4.y; m3.z += a3*w4.z; m3.w += a3*w4.w;
            }
        }
        mx.x = fmaxf(fmaxf(fmaxf(fmaxf(mx.x, m0.x), m1.x), m2.x), m3.x);
        mx.y = fmaxf(fmaxf(fmaxf(fmaxf(mx.y, m0.y), m1.y), m2.y), m3.y);
        mx.z = fmaxf(fmaxf(fmaxf(fmaxf(mx.z, m0.z), m1.z), m2.z), m3.z);
        mx.w = fmaxf(fmaxf(fmaxf(fmaxf(mx.w, m0.w), m1.w), m2.w), m3.w);
    }

    *(float4*)(outp + (size_t)q*OUT_ + c4) = mx;
}

// ---------------------------------------------------------------------------
extern "C" void kernel_launch(void* const* d_in, const int* in_sizes, int n_in,
                              void* d_out, int out_size)
{
    const float* x   = (const float*)d_in[0];
    const float* pos = (const float*)d_in[1];
    const float* lfr = (const float*)d_in[2];
    const float* W1  = (const float*)d_in[4];
    const float* b1  = (const float*)d_in[5];
    const float* W2  = (const float*)d_in[6];
    const float* b2  = (const float*)d_in[7];
    float* outp = (float*)d_out;

    const int knn_smem = (QB_*ROWQ_ + 2*TK_*ROWQ_ + 2*TK_ + 2*TK_) * 4; // 27648 B
    cudaFuncSetAttribute(k_knn_i8, cudaFuncAttributeMaxDynamicSharedMemorySize, knn_smem);

    k_prep<<<(B_*N_ + 255)/256, 256>>>(x, pos, lfr, outp, out_size);
    k_knn_i8<<<NQ_/QB_, 256, knn_smem>>>();
    k_rerank<<<NQ_/8, 256>>>();
    k_mlp<<<NQ_/8, 256>>>(x, lfr, W1, b1, W2, b2, outp);
}

// round 14
// speedup vs baseline: 1.1281x; 1.0607x over previous
#include <cuda_runtime.h>
#include <math_constants.h>
#include <stdint.h>

#define B_      4
#define N_      16384
#define STRIDE_ 4
#define K_      20
#define K2_     32          // screening candidate count
#define D_      64
#define DK_     67
#define KFS_    68
#define M_      4096
#define NQ_     (B_*M_)     // 16384
#define HID_    128
#define OUT_    128
#define TK_     128         // keys per tile
#define QB_     64          // queries per block (8 warps x 8)
#define ROWQ_   20          // uints per int8 feature row (68 dims + 12 pad)

// scratch (no cudaMalloc allowed)
__device__ float    g_kf[(size_t)B_*N_*KFS_];   // fp32 features (pad=0) for exact rerank
__device__ uint32_t g_kfq[(size_t)B_*N_*ROWQ_]; // int8 features (pads=0) for screening
__device__ float    g_kn[B_*N_];                // key squared norms (fp32)
__device__ float    g_ksc[B_*N_];               // per-row quant scale
__device__ int      g_cand[NQ_*K2_];            // screening candidates
__device__ int      g_nbr[NQ_*K_];              // exact neighbor indices

// monotone float -> uint key (handles negatives); inverse
static __device__ __forceinline__ uint32_t fkey_(float x) {
    uint32_t u = __float_as_uint(x);
    return u ^ (uint32_t)(((int)u >> 31) | 0x80000000);
}
static __device__ __forceinline__ float funkey_(uint32_t k) {
    uint32_t u = (k & 0x80000000u) ? (k ^ 0x80000000u) : ~k;
    return __uint_as_float(u);
}
static __device__ __forceinline__ uint32_t redux_max_(uint32_t v) {
    uint32_t r; asm("redux.sync.max.u32 %0,%1,0xffffffff;" : "=r"(r) : "r"(v)); return r;
}

// ---------------------------------------------------------------------------
// Kernel 1: per-point transform -> kf (fp32 + int8), norms, scale, passthrough
// (byte-identical to R13)
// ---------------------------------------------------------------------------
__global__ void __launch_bounds__(256) k_prep(const float* __restrict__ x,
                                              const float* __restrict__ pos,
                                              const float* __restrict__ lfr,
                                              float* __restrict__ outp,
                                              int out_size)
{
    int n = blockIdx.x * blockDim.x + threadIdx.x;
    if (n >= B_*N_) return;
    const float* xr = x + (size_t)n * D_;
    const float* R  = lfr + (size_t)n * 9;
    float r[9];
#pragma unroll
    for (int i = 0; i < 9; i++) r[i] = R[i];

    float kf[KFS_];
#pragma unroll
    for (int i = 0; i < 16; i++) kf[i] = xr[i];
#pragma unroll
    for (int v = 0; v < 16; v++) {
        float b0 = xr[16+3*v+0], b1 = xr[16+3*v+1], b2 = xr[16+3*v+2];
#pragma unroll
        for (int a = 0; a < 3; a++)
            kf[16+3*v+a] = r[0*3+a]*b0 + r[1*3+a]*b1 + r[2*3+a]*b2;
    }
    float p0 = pos[n*3+0], p1 = pos[n*3+1], p2 = pos[n*3+2];
    kf[64] = p0; kf[65] = p1; kf[66] = p2; kf[67] = 0.f;

    float s = 0.f, mxv = 1e-20f;
#pragma unroll
    for (int i = 0; i < KFS_; i++) {
        g_kf[(size_t)n*KFS_ + i] = kf[i];
        s += kf[i]*kf[i];
        mxv = fmaxf(mxv, fabsf(kf[i]));
    }
    g_kn[n] = s;

    const float inv = 127.f / mxv;
    g_ksc[n] = mxv * (1.f/127.f);
    uint32_t* qr = g_kfq + (size_t)n*ROWQ_;
#pragma unroll
    for (int g = 0; g < 17; g++) {
        int a0 = __float2int_rn(kf[4*g+0]*inv);
        int a1 = __float2int_rn(kf[4*g+1]*inv);
        int a2 = __float2int_rn(kf[4*g+2]*inv);
        int a3 = __float2int_rn(kf[4*g+3]*inv);
        qr[g] = (uint32_t)(a0 & 0xff) | ((uint32_t)(a1 & 0xff) << 8)
              | ((uint32_t)(a2 & 0xff) << 16) | ((uint32_t)a3 << 24);
    }
    qr[17] = 0u; qr[18] = 0u; qr[19] = 0u;

    if ((n & 3) == 0) {
        int b   = n >> 14;
        int qid = b*M_ + ((n & (N_-1)) >> 2);
        const int off_pos = NQ_*OUT_;
        const int off_bat = off_pos + NQ_*3;
        const int off_lf  = off_bat + NQ_;
        if (out_size >= off_lf + NQ_*9) {
            float* pos_out = outp + off_pos;
            float* bat_out = outp + off_bat;
            float* lf_out  = outp + off_lf;
            pos_out[qid*3+0] = p0; pos_out[qid*3+1] = p1; pos_out[qid*3+2] = p2;
            bat_out[qid] = (float)b;
#pragma unroll
            for (int i = 0; i < 9; i++) lf_out[qid*9+i] = r[i];
        }
    }
}

// ---------------------------------------------------------------------------
// Warp-distributed top-32 insert — redux.sync based (proven)
// ---------------------------------------------------------------------------
__device__ __forceinline__ void topk_insert(float d2, int gidx,
                                            uint32_t& kdk, int& ki, float& th, int lane)
{
    unsigned m = __ballot_sync(0xffffffffu, d2 < th);
    while (m) {
        int src = __ffs(m) - 1; m &= m - 1;
        float v  = __shfl_sync(0xffffffffu, d2,  src);
        int   vi = __shfl_sync(0xffffffffu, gidx, src);
        if (v < th) {
            uint32_t mx = redux_max_(kdk);
            unsigned vict = __ballot_sync(0xffffffffu, kdk == mx);
            int ml = __ffs(vict) - 1;
            if (lane == ml) { kdk = fkey_(v); ki = vi; }
            th = funkey_(redux_max_(kdk));
        }
    }
}

// ---------------------------------------------------------------------------
// Kernel 2: int8 dp4a screening KNN (byte-identical to R13)
// ---------------------------------------------------------------------------
__global__ void __launch_bounds__(256) k_knn_i8()
{
    extern __shared__ uint32_t sh[];
    uint32_t* skq  = sh;                              // [QB_][20]
    uint32_t* skey = sh + QB_*ROWQ_;                  // [2][TK_][20]
    float*    skn  = (float*)(sh + QB_*ROWQ_ + 2*TK_*ROWQ_);          // [2][TK_]
    float*    ssc  = (float*)(sh + QB_*ROWQ_ + 2*TK_*ROWQ_ + 2*TK_);  // [2][TK_]

    const int tid = threadIdx.x, lane = tid & 31, w = tid >> 5;
    const int qbase = blockIdx.x * QB_;
    const int b = qbase >> 12;
    const int kb0 = b * N_;

    for (int i = tid; i < QB_*5; i += 256) {
        int row = i / 5, g = i - row*5;
        int pt = kb0 + ((qbase + row) - b*M_) * STRIDE_;
        *(uint4*)(skq + row*ROWQ_ + 4*g) = *(const uint4*)(g_kfq + (size_t)pt*ROWQ_ + 4*g);
    }
    for (int i = tid; i < TK_*5; i += 256) {
        int row = i / 5, g = i - row*5;
        *(uint4*)(skey + row*ROWQ_ + 4*g) = *(const uint4*)(g_kfq + (size_t)(kb0 + row)*ROWQ_ + 4*g);
    }
    if (tid < TK_) { skn[tid] = g_kn[kb0 + tid]; ssc[tid] = g_ksc[kb0 + tid]; }

    float sq[8];
#pragma unroll
    for (int j = 0; j < 8; j++)
        sq[j] = g_ksc[kb0 + ((qbase + w*8 + j) - b*M_) * STRIDE_];

    uint32_t kdk[8];
    float th[8];
    int   ki[8];
    const uint32_t KINF = fkey_(CUDART_INF_F);
#pragma unroll
    for (int j = 0; j < 8; j++) { kdk[j] = KINF; ki[j] = 0; th[j] = CUDART_INF_F; }
    const uint32_t* qb = skq + (w*8)*ROWQ_;

    __syncthreads();

    for (int t = 0; t < N_/TK_; t++) {
        const int buf = t & 1;
        if (t + 1 < N_/TK_) {
            uint32_t* dst = skey + (buf^1)*TK_*ROWQ_;
            const uint32_t* src = g_kfq + (size_t)(kb0 + (t+1)*TK_)*ROWQ_;
            for (int i = tid; i < TK_*5; i += 256) {
                int row = i / 5, g = i - row*5;
                *(uint4*)(dst + row*ROWQ_ + 4*g) = *(const uint4*)(src + (size_t)row*ROWQ_ + 4*g);
            }
            if (tid < TK_) {
                skn[(buf^1)*TK_ + tid] = g_kn[kb0 + (t+1)*TK_ + tid];
                ssc[(buf^1)*TK_ + tid] = g_ksc[kb0 + (t+1)*TK_ + tid];
            }
        }

        const uint32_t* kb = skey + buf*TK_*ROWQ_;
        int acc[8][4];
#pragma unroll
        for (int q = 0; q < 8; q++) { acc[q][0]=0; acc[q][1]=0; acc[q][2]=0; acc[q][3]=0; }

#pragma unroll
        for (int g = 0; g < 5; g++) {
            uint4 k0 = *(const uint4*)(kb + (lane     )*ROWQ_ + 4*g);
            uint4 k1 = *(const uint4*)(kb + (lane + 32)*ROWQ_ + 4*g);
            uint4 k2 = *(const uint4*)(kb + (lane + 64)*ROWQ_ + 4*g);
            uint4 k3 = *(const uint4*)(kb + (lane + 96)*ROWQ_ + 4*g);
#pragma unroll
            for (int q = 0; q < 8; q++) {
                uint4 qv = *(const uint4*)(qb + q*ROWQ_ + 4*g);   // broadcast LDS.128
                acc[q][0] = __dp4a((int)qv.x, (int)k0.x, acc[q][0]);
                acc[q][1] = __dp4a((int)qv.x, (int)k1.x, acc[q][1]);
                acc[q][2] = __dp4a((int)qv.x, (int)k2.x, acc[q][2]);
                acc[q][3] = __dp4a((int)qv.x, (int)k3.x, acc[q][3]);
                acc[q][0] = __dp4a((int)qv.y, (int)k0.y, acc[q][0]);
                acc[q][1] = __dp4a((int)qv.y, (int)k1.y, acc[q][1]);
                acc[q][2] = __dp4a((int)qv.y, (int)k2.y, acc[q][2]);
                acc[q][3] = __dp4a((int)qv.y, (int)k3.y, acc[q][3]);
                acc[q][0] = __dp4a((int)qv.z, (int)k0.z, acc[q][0]);
                acc[q][1] = __dp4a((int)qv.z, (int)k1.z, acc[q][1]);
                acc[q][2] = __dp4a((int)qv.z, (int)k2.z, acc[q][2]);
                acc[q][3] = __dp4a((int)qv.z, (int)k3.z, acc[q][3]);
                acc[q][0] = __dp4a((int)qv.w, (int)k0.w, acc[q][0]);
                acc[q][1] = __dp4a((int)qv.w, (int)k1.w, acc[q][1]);
                acc[q][2] = __dp4a((int)qv.w, (int)k2.w, acc[q][2]);
                acc[q][3] = __dp4a((int)qv.w, (int)k3.w, acc[q][3]);
            }
        }

        const float* knb = skn + buf*TK_;
        const float* scb = ssc + buf*TK_;
        const float kn0 = knb[lane], kn1 = knb[lane+32], kn2 = knb[lane+64], kn3 = knb[lane+96];
        const float c0 = -2.f*scb[lane],    c1 = -2.f*scb[lane+32];
        const float c2 = -2.f*scb[lane+64], c3 = -2.f*scb[lane+96];
        const int gi = kb0 + t*TK_ + lane;
#pragma unroll
        for (int q = 0; q < 8; q++) {
            float d20 = fmaf((float)acc[q][0], sq[q]*c0, kn0);
            float d21 = fmaf((float)acc[q][1], sq[q]*c1, kn1);
            float d22 = fmaf((float)acc[q][2], sq[q]*c2, kn2);
            float d23 = fmaf((float)acc[q][3], sq[q]*c3, kn3);
            float mn = fminf(fminf(d20, d21), fminf(d22, d23));
            if (__ballot_sync(0xffffffffu, mn < th[q])) {
                topk_insert(d20, gi,    kdk[q], ki[q], th[q], lane);
                topk_insert(d21, gi+32, kdk[q], ki[q], th[q], lane);
                topk_insert(d22, gi+64, kdk[q], ki[q], th[q], lane);
                topk_insert(d23, gi+96, kdk[q], ki[q], th[q], lane);
            }
        }
        __syncthreads();
    }

#pragma unroll
    for (int q = 0; q < 8; q++)
        g_cand[(size_t)(qbase + w*8 + q)*K2_ + lane] = ki[q];
}

// ---------------------------------------------------------------------------
// Kernel 2b: exact fp32 re-rank of 32 candidates -> top-20 set.
// ---------------------------------------------------------------------------
__global__ void __launch_bounds__(256) k_rerank()
{
    const int tid = threadIdx.x, lane = tid & 31, w = tid >> 5;
    const int q = blockIdx.x * 8 + w;
    const int b = q >> 12;
    const int pt = b*N_ + (q - b*M_) * STRIDE_;

    const int cand = g_cand[(size_t)q*K2_ + lane];
    const float4* qr = (const float4*)(g_kf + (size_t)pt*KFS_);
    const float4* kr = (const float4*)(g_kf + (size_t)cand*KFS_);
    float dot = 0.f;
#pragma unroll
    for (int g = 0; g < 17; g++) {
        float4 a = qr[g], c = kr[g];
        dot = fmaf(a.x,c.x, fmaf(a.y,c.y, fmaf(a.z,c.z, fmaf(a.w,c.w, dot))));
    }
    float d2 = g_kn[cand] - 2.f*dot;

#pragma unroll
    for (int r = 0; r < K_; r++) {
        float mv = d2; int ml = lane;
#pragma unroll
        for (int off = 16; off; off >>= 1) {
            float om = __shfl_xor_sync(0xffffffffu, mv, off);
            int   ol = __shfl_xor_sync(0xffffffffu, ml, off);
            if (om < mv || (om == mv && ol < ml)) { mv = om; ml = ol; }
        }
        if (lane == ml) { g_nbr[q*K_ + r] = cand; d2 = CUDART_INF_F; }
    }
}

// ---------------------------------------------------------------------------
// Kernel 3: edge MLP + maxpool — 8 edges per weight pass (3 groups, padded).
// Block = 128 thr = 4 warps; warp = 1 query. Weight L1 traffic -40%.
// ---------------------------------------------------------------------------
__global__ void __launch_bounds__(128, 6) k_mlp(const float* __restrict__ x,
                                                const float* __restrict__ lfr,
                                                const float* __restrict__ W1,
                                                const float* __restrict__ b1,
                                                const float* __restrict__ W2,
                                                const float* __restrict__ b2,
                                                float* __restrict__ outp)
{
    __shared__ __align__(16) float sxd[4][D_];
    __shared__ float slf[4][12];
    __shared__ __align__(16) float srel[4][8][D_];
    __shared__ __align__(16) float srl[4][8][D_];
    __shared__ __align__(16) float sa1[4][8][HID_];

    const int tid = threadIdx.x, lane = tid & 31, w = tid >> 5;
    const int q  = blockIdx.x * 4 + w;
    const int b  = q >> 12;
    const int pt = b*N_ + (q - b*M_) * STRIDE_;

    for (int d = lane; d < D_; d += 32) sxd[w][d] = x[(size_t)pt*D_ + d];
    if (lane < 9) slf[w][lane] = lfr[(size_t)pt*9 + lane];
    __syncwarp();

    const int c4 = lane * 4;
    float4 base = *(const float4*)(b1 + c4);
#pragma unroll 8
    for (int d = 0; d < D_; d++) {
        float xv = sxd[w][d];
        float4 w4 = __ldg((const float4*)(W1 + d*HID_ + c4));
        base.x += xv*w4.x; base.y += xv*w4.y; base.z += xv*w4.z; base.w += xv*w4.w;
    }
    const float4 b2v = __ldg((const float4*)(b2 + c4));
    float4 mx = make_float4(-CUDART_INF_F, -CUDART_INF_F, -CUDART_INF_F, -CUDART_INF_F);

    for (int grp = 0; grp < 3; grp++) {
        __syncwarp();
        int s = 0;
        if (lane < 8) {
            int ei = grp*8 + lane;
            if (ei > K_-1) ei = K_-1;            // pad with duplicates (max-pool safe)
            s = g_nbr[q*K_ + ei];
        }
        int ss[8];
#pragma unroll
        for (int e = 0; e < 8; e++) ss[e] = __shfl_sync(0xffffffffu, s, e);

        // srel for 8 edges: lane covers dims {lane, lane+32}
#pragma unroll
        for (int e = 0; e < 8; e++) {
            const float* xs = x + (size_t)ss[e] * D_;
#pragma unroll
            for (int d = lane; d < D_; d += 32)
                srel[w][e][d] = xs[d] - sxd[w][d];
        }
        __syncwarp();
        // rotate rel -> rel_local with R = lf_dst (8 edges x 64 dims = 16 items/lane)
#pragma unroll
        for (int t = 0; t < 16; t++) {
            int item = lane + 32*t;
            int e = item >> 6;
            int d = item & 63;
            float v;
            if (d < 16) v = srel[w][e][d];
            else {
                int dd = d - 16;
                int a  = dd % 3;
                int vb = 16 + dd - a;
                v = slf[w][a*3+0]*srel[w][e][vb]
                  + slf[w][a*3+1]*srel[w][e][vb+1]
                  + slf[w][a*3+2]*srel[w][e][vb+2];
            }
            srl[w][e][d] = v;
        }
        __syncwarp();

        // layer 1 (bottom half of W1), 8 edges per weight load
        float4 ac[8];
#pragma unroll
        for (int e = 0; e < 8; e++) ac[e] = make_float4(0.f, 0.f, 0.f, 0.f);
#pragma unroll 1
        for (int d = 0; d < D_; d += 4) {
            float4 rv[8];
#pragma unroll
            for (int e = 0; e < 8; e++) rv[e] = *(const float4*)&srl[w][e][d];
#pragma unroll
            for (int dd = 0; dd < 4; dd++) {
                float4 w4 = __ldg((const float4*)(W1 + (D_+d+dd)*HID_ + c4));
#pragma unroll
                for (int e = 0; e < 8; e++) {
                    float a = (&rv[e].x)[dd];
                    ac[e].x += a*w4.x; ac[e].y += a*w4.y; ac[e].z += a*w4.z; ac[e].w += a*w4.w;
                }
            }
        }
#pragma unroll
        for (int e = 0; e < 8; e++) {
            float4 a;
            a.x = fmaxf(base.x + ac[e].x, 0.f);
            a.y = fmaxf(base.y + ac[e].y, 0.f);
            a.z = fmaxf(base.z + ac[e].z, 0.f);
            a.w = fmaxf(base.w + ac[e].w, 0.f);
            *(float4*)&sa1[w][e][c4] = a;
        }
        __syncwarp();

        // layer 2, 8 edges per weight load
        float4 m[8];
#pragma unroll
        for (int e = 0; e < 8; e++) m[e] = b2v;
#pragma unroll 1
        for (int j = 0; j < HID_; j += 4) {
            float4 av[8];
#pragma unroll
            for (int e = 0; e < 8; e++) av[e] = *(const float4*)&sa1[w][e][j];
#pragma unroll
            for (int jj = 0; jj < 4; jj++) {
                float4 w4 = __ldg((const float4*)(W2 + (j+jj)*HID_ + c4));
#pragma unroll
                for (int e = 0; e < 8; e++) {
                    float a = (&av[e].x)[jj];
                    m[e].x += a*w4.x; m[e].y += a*w4.y; m[e].z += a*w4.z; m[e].w += a*w4.w;
                }
            }
        }
#pragma unroll
        for (int e = 0; e < 8; e++) {
            mx.x = fmaxf(mx.x, m[e].x);
            mx.y = fmaxf(mx.y, m[e].y);
            mx.z = fmaxf(mx.z, m[e].z);
            mx.w = fmaxf(mx.w, m[e].w);
        }
    }

    *(float4*)(outp + (size_t)q*OUT_ + c4) = mx;
}

// ---------------------------------------------------------------------------
extern "C" void kernel_launch(void* const* d_in, const int* in_sizes, int n_in,
                              void* d_out, int out_size)
{
    const float* x   = (const float*)d_in[0];
    const float* pos = (const float*)d_in[1];
    const float* lfr = (const float*)d_in[2];
    const float* W1  = (const float*)d_in[4];
    const float* b1  = (const float*)d_in[5];
    const float* W2  = (const float*)d_in[6];
    const float* b2  = (const float*)d_in[7];
    float* outp = (float*)d_out;

    const int knn_smem = (QB_*ROWQ_ + 2*TK_*ROWQ_ + 2*TK_ + 2*TK_) * 4; // 27648 B
    cudaFuncSetAttribute(k_knn_i8, cudaFuncAttributeMaxDynamicSharedMemorySize, knn_smem);

    k_prep<<<(B_*N_ + 255)/256, 256>>>(x, pos, lfr, outp, out_size);
    k_knn_i8<<<NQ_/QB_, 256, knn_smem>>>();
    k_rerank<<<NQ_/8, 256>>>();
    k_mlp<<<NQ_/4, 128>>>(x, lfr, W1, b1, W2, b2, outp);
}